// round 8
// baseline (speedup 1.0000x reference)
#include <cuda_runtime.h>

// Problem shape fixed by setup_inputs(): x = (2, 4, 8, 256, 256) float32.
#define DD   8
#define HH   256
#define WW   256
#define NBC  8
#define HWsz 65536
#define DHWs 524288                  // 2^19
#define HT   8                       // h-rows per warp tile
#define WT   128                     // w columns per warp tile (float4 x 32)
#define MAIN_WARPS (NBC * 6 * 32 * 2)    // 3072
#define COPY_WARPS (NBC * 2 * 32 * 2)    // 1024
#define MAIN_BLOCKS (MAIN_WARPS / 2)     // 1536
#define COPY_BLOCKS (COPY_WARPS / 2)     // 512

#define MAX_SHIFT 0.6f
#define BONUS     10.0f

// One Newton step. Returns 0 = moved, 1 = converged (valid), 2 = invalid.
__device__ __forceinline__ int quad_step(
    float c000, float pxm, float pxp, float pym, float pyp, float psm, float psp,
    float e011, float e01m, float e0m1, float e0mm,
    float e101, float e10m, float em01, float em0m,
    float e110, float e1m0, float em10, float emm0,
    int& dc, int& hc, int& wc,
    float& shx, float& shy, float& shs, float& gds)
{
    float gx = 0.5f * (pxp - pxm);
    float gy = 0.5f * (pyp - pym);
    float gs = 0.5f * (psp - psm);
    float dxx = pxp - 2.0f * c000 + pxm;
    float dyy = pyp - 2.0f * c000 + pym;
    float dss = psp - 2.0f * c000 + psm;
    float dxy = 0.25f * (e011 - e01m - e0m1 + e0mm);
    float dxs = 0.25f * (e101 - e10m - em01 + em0m);
    float dys = 0.25f * (e110 - e1m0 - em10 + emm0);

    float cf00 = dyy * dss - dys * dys;
    float cf01 = dxy * dss - dys * dxs;
    float cf02 = dxy * dys - dyy * dxs;
    float det  = dxx * cf00 - dxy * cf01 + dxs * cf02;
    if (!(fabsf(det) > 0.0f)) return 2;

    float r0 = -gx, r1 = -gy, r2 = -gs;
    float sx = (r0 * cf00 - dxy * (r1 * dss - dys * r2) + dxs * (r1 * dys - dyy * r2)) / det;
    float sy = (dxx * (r1 * dss - dys * r2) - r0 * cf01 + dxs * (dxy * r2 - r1 * dxs)) / det;
    float ss = (dxx * (dyy * r2 - r1 * dys) - dxy * (dxy * r2 - r1 * dxs) + r0 * cf02) / det;

    shx = sx; shy = sy; shs = ss;
    gds = gx * sx + gy * sy + gs * ss;

    int mvx = (sx > MAX_SHIFT) ? 1 : ((sx < -MAX_SHIFT) ? -1 : 0);
    int nw = wc + mvx;
    if (nw < 1 || nw > WW - 2) return 2;
    wc = nw;
    int mvy = (sy > MAX_SHIFT) ? 1 : ((sy < -MAX_SHIFT) ? -1 : 0);
    int nh = hc + mvy;
    if (nh < 1 || nh > HH - 2) return 2;
    hc = nh;
    int mvs = (ss > MAX_SHIFT) ? 1 : ((ss < -MAX_SHIFT) ? -1 : 0);
    int nd = dc + mvs;
    if (nd < 1 || nd > DD - 2) return 2;
    dc = nd;

    return ((mvx | mvy | mvs) == 0) ? 1 : 0;
}

__global__ __launch_bounds__(64)
void iqi3d_kernel(const float* __restrict__ x, float* __restrict__ out)
{
    const int lane = threadIdx.x & 31;
    const int wid  = threadIdx.x >> 5;
    const int gw   = blockIdx.x * 2 + wid;   // global warp id

    __shared__ unsigned short slist[2][256]; // Chebyshev packing bound for 8x128
    unsigned short* wl = slist[wid];

    if (gw < MAIN_WARPS) {
        // ===== phase 1: barrier-free mask + defaults + warp-local list =====
        const int wt = gw & 1;
        const int t  = (gw >> 1) & 31;
        const int q  = gw >> 6;               // 0..47
        const int d  = (q % 6) + 1;           // 1..6
        const int bc = q / 6;
        const int h0 = t * HT;
        const int wbase = wt * WT;
        const int w0 = wbase + (lane << 2);

        const float* __restrict__ xb  = x + (size_t)bc * DHWs;
        const float4* __restrict__ xb4 = (const float4*)xb;
        int cnt = 0;

        // rolling window Wn[dd][hh] (float4 = 4 w columns)
        float4 Wn[3][3];
        float  E[3][3];                        // edge column (lanes 0/31 only)
        const bool epred = (lane == 0) | (lane == 31);
        int ecol = (lane == 0) ? (wbase - 1) : (wbase + WT);
        if (ecol < 0) ecol = 0;
        if (ecol > WW - 1) ecol = WW - 1;

        const int fbase4 = d * (HWsz / 4) + (wbase >> 2) + lane;
        {
            int hm = h0 - 1; if (hm < 0) hm = 0;
            const int hs[3] = { hm, h0, h0 + 1 };
#pragma unroll
            for (int dd = 0; dd < 3; ++dd) {
                const int off = fbase4 + (dd - 1) * (HWsz / 4);
#pragma unroll
                for (int hh = 0; hh < 3; ++hh)
                    Wn[dd][hh] = xb4[off + hs[hh] * 64];
                E[dd][0] = E[dd][1] = E[dd][2] = 0.0f;
            }
            if (epred) {
#pragma unroll
                for (int dd = 0; dd < 3; ++dd) {
                    const float* ep = xb + (d + dd - 1) * HWsz + ecol;
#pragma unroll
                    for (int hh = 0; hh < 3; ++hh)
                        E[dd][hh] = ep[hs[hh] * WW];
                }
            }
        }

        float* __restrict__ ob = out + (size_t)bc * 3 * DHWs + d * HWsz + h0 * WW;
        float* __restrict__ oy = out + (size_t)NBC * 3 * DHWs + (size_t)bc * DHWs
                                     + d * HWsz + h0 * WW;
        const float fdd = (float)d;
        const float4 wcoord = make_float4((float)w0, (float)(w0 + 1),
                                          (float)(w0 + 2), (float)(w0 + 3));

#pragma unroll
        for (int r = 0; r < HT; ++r) {
            const int h = h0 + r;

            // prefetch next row (consumed a full body later)
            float4 N[3]; float EN[3];
            if (r < HT - 1) {
                int hn = h + 2; if (hn > HH - 1) hn = HH - 1;
#pragma unroll
                for (int dd = 0; dd < 3; ++dd)
                    N[dd] = xb4[fbase4 + (dd - 1) * (HWsz / 4) + hn * 64];
                if (epred) {
#pragma unroll
                    for (int dd = 0; dd < 3; ++dd)
                        EN[dd] = xb[(d + dd - 1) * HWsz + hn * WW + ecol];
                }
            }

            // per-column 26-neighbor (in-column) exclusive/inclusive maxes
            const float* W = reinterpret_cast<const float*>(Wn);
            float ex[4], cc[4], full[4];
#pragma unroll
            for (int j = 0; j < 4; ++j) {
                float m = W[0 * 4 + j];                       // (0,0)
                m = fmaxf(m, W[1 * 4 + j]);                   // (0,1)
                m = fmaxf(m, W[2 * 4 + j]);                   // (0,2)
                m = fmaxf(m, W[3 * 4 + j]);                   // (1,0)
                m = fmaxf(m, W[5 * 4 + j]);                   // (1,2)
                m = fmaxf(m, W[6 * 4 + j]);                   // (2,0)
                m = fmaxf(m, W[7 * 4 + j]);                   // (2,1)
                m = fmaxf(m, W[8 * 4 + j]);                   // (2,2)
                ex[j] = m;
                cc[j] = W[4 * 4 + j];                         // center (1,1)
                full[j] = fmaxf(m, cc[j]);
            }

            // edge column full-max (lanes 0/31 only)
            float ef = fmaxf(E[0][0], E[0][1]); ef = fmaxf(ef, E[0][2]);
            ef = fmaxf(ef, E[1][0]); ef = fmaxf(ef, E[1][1]); ef = fmaxf(ef, E[1][2]);
            ef = fmaxf(ef, E[2][0]); ef = fmaxf(ef, E[2][1]); ef = fmaxf(ef, E[2][2]);

            float fl = __shfl_up_sync(0xffffffffu, full[3], 1);
            float fr = __shfl_down_sync(0xffffffffu, full[0], 1);
            if (lane == 0)  fl = ef;
            if (lane == 31) fr = ef;

            const bool hin = (h >= 1) & (h <= HH - 2);
            bool mk[4];
            mk[0] = hin & (w0 >= 1)           & (cc[0] > fmaxf(ex[0], fmaxf(fl,      full[1])));
            mk[1] = hin                        & (cc[1] > fmaxf(ex[1], fmaxf(full[0], full[2])));
            mk[2] = hin                        & (cc[2] > fmaxf(ex[2], fmaxf(full[1], full[3])));
            mk[3] = hin & (w0 + 3 <= WW - 2)  & (cc[3] > fmaxf(ex[3], fmaxf(full[2], fr)));

            // warp-local list append (ballot cumsum, no atomics)
            const unsigned lt = (1u << lane) - 1u;
#pragma unroll
            for (int j = 0; j < 4; ++j) {
                unsigned b = __ballot_sync(0xffffffffu, mk[j]);
                if (mk[j]) wl[cnt + __popc(b & lt)] =
                    (unsigned short)((r << 8) | (w0 + j));
                cnt += __popc(b);
            }

            // default outputs; phase 2 overwrites valid maxima
            const float fhh = (float)h;
            const int ro = r * WW + w0;
            *(float4*)&ob[0 * DHWs + ro] = make_float4(fdd, fdd, fdd, fdd);
            *(float4*)&ob[1 * DHWs + ro] = wcoord;
            *(float4*)&ob[2 * DHWs + ro] = make_float4(fhh, fhh, fhh, fhh);
            *(float4*)&oy[ro]            = Wn[1][1];

            // roll windows by one row
#pragma unroll
            for (int dd = 0; dd < 3; ++dd) {
                Wn[dd][0] = Wn[dd][1]; Wn[dd][1] = Wn[dd][2]; Wn[dd][2] = N[dd];
                E[dd][0]  = E[dd][1];  E[dd][1]  = E[dd][2];  E[dd][2]  = EN[dd];
            }
        }

        // ===== phase 2: cooperative refine over the warp's compacted list =====
        __syncwarp();
#pragma unroll 1
        for (int i = lane; i < cnt; i += 32) {
            const int code = wl[i];
            const int r = code >> 8;
            const int w = code & 255;
            const int h = h0 + r;
            const int sp = d * HWsz + h * WW + w;

            int dc = d, hc = h, wc = w;
            float shx = 0.f, shy = 0.f, shs = 0.f, gds = 0.f;
            int st = 0;

#pragma unroll 1
            for (int itn = 0; (itn < 5) && (st == 0); ++itn) {
                int ds_ = min(max(dc, 1), DD - 2);
                int hs_ = min(max(hc, 1), HH - 2);
                int ws_ = min(max(wc, 1), WW - 2);
                const float* pp = xb + ds_ * HWsz + hs_ * WW + ws_;
                st = quad_step(pp[0],
                    pp[-1], pp[1], pp[-WW], pp[WW], pp[-HWsz], pp[HWsz],
                    pp[WW + 1], pp[WW - 1], pp[-WW + 1], pp[-WW - 1],
                    pp[HWsz + 1], pp[HWsz - 1], pp[-HWsz + 1], pp[-HWsz - 1],
                    pp[HWsz + WW], pp[HWsz - WW], pp[-HWsz + WW], pp[-HWsz - WW],
                    dc, hc, wc, shx, shy, shs, gds);
            }

            bool valid = (st != 2)
                       && (fabsf(shx) <= 1.5f) && (fabsf(shy) <= 1.5f) && (fabsf(shs) <= 1.5f);
            if (valid) {
                const int cb = bc * 3 * DHWs;
                out[cb + 0 * DHWs + sp] = (float)dc + shs;
                out[cb + 1 * DHWs + sp] = (float)wc + shx;
                out[cb + 2 * DHWs + sp] = (float)hc + shy;
                out[(size_t)NBC * 3 * DHWs + (size_t)bc * DHWs + sp] =
                    xb[sp] + (0.5f * gds + BONUS);
            }
        }
    } else {
        // ---------- copy path: d = 0 and d = 7 are pure defaults ----------
        const int g2 = gw - MAIN_WARPS;          // 0..1023
        const int wt = g2 & 1;
        const int t  = (g2 >> 1) & 31;
        const int s  = g2 >> 6;
        const int d  = (s & 1) ? (DD - 1) : 0;
        const int bc = s >> 1;
        const int h0 = t * HT;
        const int wbase = wt * WT;
        const int w0 = wbase + (lane << 2);

        const float4* __restrict__ xb4 = (const float4*)(x + (size_t)bc * DHWs);
        float* __restrict__ ob = out + (size_t)bc * 3 * DHWs + d * HWsz;
        float* __restrict__ oy = out + (size_t)NBC * 3 * DHWs + (size_t)bc * DHWs
                                     + d * HWsz;
        const float fdd = (float)d;
        const float4 wcoord = make_float4((float)w0, (float)(w0 + 1),
                                          (float)(w0 + 2), (float)(w0 + 3));
        const int base4 = d * (HWsz / 4) + (wbase >> 2) + lane;

#pragma unroll
        for (int r = 0; r < HT; ++r) {
            const int h = h0 + r;
            const float4 c = xb4[base4 + h * 64];
            const float fh = (float)h;
            const int off = h * WW + w0;
            *(float4*)&ob[0 * DHWs + off] = make_float4(fdd, fdd, fdd, fdd);
            *(float4*)&ob[1 * DHWs + off] = wcoord;
            *(float4*)&ob[2 * DHWs + off] = make_float4(fh, fh, fh, fh);
            *(float4*)&oy[off] = c;
        }
    }
}

extern "C" void kernel_launch(void* const* d_in, const int* in_sizes, int n_in,
                              void* d_out, int out_size)
{
    (void)in_sizes; (void)n_in; (void)out_size;
    const float* x = (const float*)d_in[0];
    float* out = (float*)d_out;
    iqi3d_kernel<<<MAIN_BLOCKS + COPY_BLOCKS, 64>>>(x, out);
}

// round 9
// speedup vs baseline: 1.0992x; 1.0992x over previous
#include <cuda_runtime.h>

// Problem shape fixed by setup_inputs(): x = (2, 4, 8, 256, 256) float32.
#define DD   8
#define HH   256
#define WW   256
#define NBC  8
#define HWsz 65536
#define DHWs 524288                  // 2^19
#define HT   8                       // h-rows per block tile
#define NTIL (HH / HT)               // 32
#define MAIN_BLOCKS (NBC * 6 * NTIL) // 1536 (interior d = 1..6)
#define COPY_BLOCKS (NBC * 2 * NTIL) // 512  (d = 0, 7: pure defaults)

#define MAX_SHIFT 0.6f
#define BONUS     10.0f

__device__ __forceinline__ float2 f2max(float2 a, float2 b) {
    return make_float2(fmaxf(a.x, b.x), fmaxf(a.y, b.y));
}

// One Newton step. Returns 0 = moved, 1 = converged (valid), 2 = invalid.
__device__ __forceinline__ int quad_step(
    float c000, float pxm, float pxp, float pym, float pyp, float psm, float psp,
    float e011, float e01m, float e0m1, float e0mm,
    float e101, float e10m, float em01, float em0m,
    float e110, float e1m0, float em10, float emm0,
    int& dc, int& hc, int& wc,
    float& shx, float& shy, float& shs, float& gds)
{
    float gx = 0.5f * (pxp - pxm);
    float gy = 0.5f * (pyp - pym);
    float gs = 0.5f * (psp - psm);
    float dxx = pxp - 2.0f * c000 + pxm;
    float dyy = pyp - 2.0f * c000 + pym;
    float dss = psp - 2.0f * c000 + psm;
    float dxy = 0.25f * (e011 - e01m - e0m1 + e0mm);
    float dxs = 0.25f * (e101 - e10m - em01 + em0m);
    float dys = 0.25f * (e110 - e1m0 - em10 + emm0);

    float cf00 = dyy * dss - dys * dys;
    float cf01 = dxy * dss - dys * dxs;
    float cf02 = dxy * dys - dyy * dxs;
    float det  = dxx * cf00 - dxy * cf01 + dxs * cf02;
    if (!(fabsf(det) > 0.0f)) return 2;

    float r0 = -gx, r1 = -gy, r2 = -gs;
    float sx = (r0 * cf00 - dxy * (r1 * dss - dys * r2) + dxs * (r1 * dys - dyy * r2)) / det;
    float sy = (dxx * (r1 * dss - dys * r2) - r0 * cf01 + dxs * (dxy * r2 - r1 * dxs)) / det;
    float ss = (dxx * (dyy * r2 - r1 * dys) - dxy * (dxy * r2 - r1 * dxs) + r0 * cf02) / det;

    shx = sx; shy = sy; shs = ss;
    gds = gx * sx + gy * sy + gs * ss;

    int mvx = (sx > MAX_SHIFT) ? 1 : ((sx < -MAX_SHIFT) ? -1 : 0);
    int nw = wc + mvx;
    if (nw < 1 || nw > WW - 2) return 2;
    wc = nw;
    int mvy = (sy > MAX_SHIFT) ? 1 : ((sy < -MAX_SHIFT) ? -1 : 0);
    int nh = hc + mvy;
    if (nh < 1 || nh > HH - 2) return 2;
    hc = nh;
    int mvs = (ss > MAX_SHIFT) ? 1 : ((ss < -MAX_SHIFT) ? -1 : 0);
    int nd = dc + mvs;
    if (nd < 1 || nd > DD - 2) return 2;
    dc = nd;

    return ((mvx | mvy | mvs) == 0) ? 1 : 0;
}

__global__ __launch_bounds__(128, 10)
void iqi3d_kernel(const float* __restrict__ x, float* __restrict__ out)
{
    const int tid = threadIdx.x;
    const int blk = blockIdx.x;
    const int lane = tid & 31;

    if (blk < MAIN_BLOCKS) {
        // =========== phase 1: mask + defaults + shared-list append ===========
        const int t  = blk & (NTIL - 1);
        const int q  = blk >> 5;
        const int d  = (q % 6) + 1;          // 1..6
        const int bc = q / 6;
        const int h0 = t * HT;

        const float* __restrict__ xb  = x + (size_t)bc * DHWs;
        const float2* __restrict__ xb2 = (const float2*)xb;
        const int w2 = tid << 1;

        __shared__ float sfull[2][2][WW];     // [iter parity][row in pair][w]
        __shared__ unsigned short slist[512]; // strict-maxima bound for 8x256
        __shared__ int scount;

        if (tid == 0) scount = 0;

        const int baseidx = d * (HWsz / 2) + tid;

        // d-folded window rows 0..3 = h-1..h+2: e = max(v[d-1],v[d+1]), c = v[d]
        float2 e[4], c[4];
        {
            int hm = h0 - 1; if (hm < 0) hm = 0;
            const int hs[4] = { hm, h0, h0 + 1, h0 + 2 };
#pragma unroll
            for (int k = 0; k < 4; ++k) {
                float2 vm = xb2[baseidx - (HWsz / 2) + hs[k] * 128];
                float2 vc = xb2[baseidx               + hs[k] * 128];
                float2 vp = xb2[baseidx + (HWsz / 2) + hs[k] * 128];
                e[k] = f2max(vm, vp);
                c[k] = vc;
            }
        }

        float* __restrict__ ob = out + (size_t)bc * 3 * DHWs + d * HWsz + h0 * WW;
        float* __restrict__ oy = out + (size_t)NBC * 3 * DHWs + (size_t)bc * DHWs
                                     + d * HWsz + h0 * WW;

        const float fw0 = (float)w2, fw1 = (float)(w2 + 1);
        const float fdd = (float)d;

#pragma unroll
        for (int it = 0; it < HT / 2; ++it) {
            const int r  = it << 1;
            const int h  = h0 + r;
            const int p  = it & 1;

            // column maxes for rows h and h+1 from the d-folded window
            const float2 m0 = f2max(e[0], c[0]);
            const float2 m1 = f2max(e[1], c[1]);
            const float2 m2 = f2max(e[2], c[2]);
            const float2 m3 = f2max(e[3], c[3]);
            const float2 t12   = f2max(m1, m2);
            const float2 fullA = f2max(m0, t12);          // incl. max, row h
            const float2 fullB = f2max(t12, m3);          // incl. max, row h+1
            const float2 exA   = f2max(f2max(m0, m2), e[1]); // excl. max, row h
            const float2 exB   = f2max(f2max(m1, m3), e[2]); // excl. max, row h+1
            const float2 cA = c[1], cB = c[2];

            *(float2*)&sfull[p][0][w2] = fullA;
            *(float2*)&sfull[p][1][w2] = fullB;

            // prefetch + d-fold the next two rows before the barrier
            float2 en0, cn0, en1, cn1;
            if (it < HT / 2 - 1) {
                int hn0 = h + 3; if (hn0 > HH - 1) hn0 = HH - 1;
                int hn1 = h + 4; if (hn1 > HH - 1) hn1 = HH - 1;
                float2 am = xb2[baseidx - (HWsz / 2) + hn0 * 128];
                float2 ac = xb2[baseidx               + hn0 * 128];
                float2 ap = xb2[baseidx + (HWsz / 2) + hn0 * 128];
                float2 bm = xb2[baseidx - (HWsz / 2) + hn1 * 128];
                float2 bcc = xb2[baseidx              + hn1 * 128];
                float2 bp = xb2[baseidx + (HWsz / 2) + hn1 * 128];
                en0 = f2max(am, ap); cn0 = ac;
                en1 = f2max(bm, bp); cn1 = bcc;
            }

            __syncthreads();
            int il = w2 - 1; if (il < 0) il = 0;
            int ir = w2 + 2; if (ir > WW - 1) ir = WW - 1;
            const float flA = sfull[p][0][il], frA = sfull[p][0][ir];
            const float flB = sfull[p][1][il], frB = sfull[p][1][ir];

            const bool hinA = (h >= 1) & (h <= HH - 2);
            const bool hinB = (h + 1 >= 1) & (h + 1 <= HH - 2);
            const bool win0 = (w2 >= 1), win1 = (w2 <= WW - 3);
            const bool mA0 = hinA & win0 & (cA.x > fmaxf(exA.x, fmaxf(flA, fullA.y)));
            const bool mA1 = hinA & win1 & (cA.y > fmaxf(exA.y, fmaxf(fullA.x, frA)));
            const bool mB0 = hinB & win0 & (cB.x > fmaxf(exB.x, fmaxf(flB, fullB.y)));
            const bool mB1 = hinB & win1 & (cB.y > fmaxf(exB.y, fmaxf(fullB.x, frB)));

            // warp-aggregated append: ONE atomic per warp per row pair
            unsigned a0 = __ballot_sync(0xffffffffu, mA0);
            unsigned a1 = __ballot_sync(0xffffffffu, mA1);
            unsigned b0 = __ballot_sync(0xffffffffu, mB0);
            unsigned b1 = __ballot_sync(0xffffffffu, mB1);
            if (a0 | a1 | b0 | b1) {
                int n = __popc(a0) + __popc(a1) + __popc(b0) + __popc(b1);
                int leader = __ffs(a0 | a1 | b0 | b1) - 1;
                int base;
                if (lane == leader) base = atomicAdd(&scount, n);
                base = __shfl_sync(0xffffffffu, base, leader);
                unsigned lt = (lane == 31) ? 0x7fffffffu : ((1u << lane) - 1u);
                const int codeA = (r << 8) | w2;
                const int codeB = ((r + 1) << 8) | w2;
                int o = base;
                if (mA0) slist[o + __popc(a0 & lt)] = (unsigned short)codeA;
                o += __popc(a0);
                if (mA1) slist[o + __popc(a1 & lt)] = (unsigned short)(codeA + 1);
                o += __popc(a1);
                if (mB0) slist[o + __popc(b0 & lt)] = (unsigned short)codeB;
                o += __popc(b0);
                if (mB1) slist[o + __popc(b1 & lt)] = (unsigned short)(codeB + 1);
            }

            // default outputs for both rows
            const int roA = r * WW + w2, roB = roA + WW;
            const float fhA = (float)h, fhB = (float)(h + 1);
            *(float2*)&ob[0 * DHWs + roA] = make_float2(fdd, fdd);
            *(float2*)&ob[1 * DHWs + roA] = make_float2(fw0, fw1);
            *(float2*)&ob[2 * DHWs + roA] = make_float2(fhA, fhA);
            *(float2*)&oy[roA]            = cA;
            *(float2*)&ob[0 * DHWs + roB] = make_float2(fdd, fdd);
            *(float2*)&ob[1 * DHWs + roB] = make_float2(fw0, fw1);
            *(float2*)&ob[2 * DHWs + roB] = make_float2(fhB, fhB);
            *(float2*)&oy[roB]            = cB;

            // roll the window by 2 rows
            e[0] = e[2]; c[0] = c[2];
            e[1] = e[3]; c[1] = c[3];
            e[2] = en0;  c[2] = cn0;
            e[3] = en1;  c[3] = cn1;
        }

        // =========== phase 2: cooperative refine over compacted list ===========
        __syncthreads();
        const int cnt = scount;
#pragma unroll 1
        for (int i = tid; i < cnt; i += 128) {
            const int code = slist[i];
            const int r = code >> 8;
            const int w = code & 255;
            const int h = h0 + r;
            const int sp = d * HWsz + h * WW + w;

            int dc = d, hc = h, wc = w;
            float shx = 0.f, shy = 0.f, shs = 0.f, gds = 0.f;
            int st = 0;

#pragma unroll 1
            for (int itn = 0; (itn < 5) && (st == 0); ++itn) {
                int ds_ = min(max(dc, 1), DD - 2);
                int hs_ = min(max(hc, 1), HH - 2);
                int ws_ = min(max(wc, 1), WW - 2);
                const float* pp = xb + ds_ * HWsz + hs_ * WW + ws_;
                st = quad_step(pp[0],
                    pp[-1], pp[1], pp[-WW], pp[WW], pp[-HWsz], pp[HWsz],
                    pp[WW + 1], pp[WW - 1], pp[-WW + 1], pp[-WW - 1],
                    pp[HWsz + 1], pp[HWsz - 1], pp[-HWsz + 1], pp[-HWsz - 1],
                    pp[HWsz + WW], pp[HWsz - WW], pp[-HWsz + WW], pp[-HWsz - WW],
                    dc, hc, wc, shx, shy, shs, gds);
            }

            bool valid = (st != 2)
                       && (fabsf(shx) <= 1.5f) && (fabsf(shy) <= 1.5f) && (fabsf(shs) <= 1.5f);
            if (valid) {
                const int cb = bc * 3 * DHWs;
                out[cb + 0 * DHWs + sp] = (float)dc + shs;
                out[cb + 1 * DHWs + sp] = (float)wc + shx;
                out[cb + 2 * DHWs + sp] = (float)hc + shy;
                out[(size_t)NBC * 3 * DHWs + (size_t)bc * DHWs + sp] =
                    xb[sp] + (0.5f * gds + BONUS);
            }
        }
    } else {
        // ---------- copy path: d = 0 and d = 7 are pure defaults ----------
        const int blk2 = blk - MAIN_BLOCKS;
        const int t  = blk2 & (NTIL - 1);
        const int q  = blk2 >> 5;
        const int d  = (q & 1) ? (DD - 1) : 0;
        const int bc = q >> 1;
        const int h0 = t * HT;

        const float4* __restrict__ xb4 =
            (const float4*)(x + (size_t)bc * DHWs + d * HWsz + h0 * WW);
        float* __restrict__ ob = out + (size_t)bc * 3 * DHWs + d * HWsz + h0 * WW;
        float* __restrict__ oy = out + (size_t)NBC * 3 * DHWs + (size_t)bc * DHWs
                                     + d * HWsz + h0 * WW;
        const float fdd = (float)d;

#pragma unroll
        for (int i = 0; i < (HT * WW / 4) / 128; ++i) {
            const int idx = i * 128 + tid;
            const int row = idx >> 6;
            const int wq  = (idx & 63) << 2;
            const float4 cc = xb4[idx];
            const float fh = (float)(h0 + row);
            const int off = row * WW + wq;
            *(float4*)&ob[0 * DHWs + off] = make_float4(fdd, fdd, fdd, fdd);
            *(float4*)&ob[1 * DHWs + off] =
                make_float4((float)wq, (float)(wq + 1), (float)(wq + 2), (float)(wq + 3));
            *(float4*)&ob[2 * DHWs + off] = make_float4(fh, fh, fh, fh);
            *(float4*)&oy[off] = cc;
        }
    }
}

extern "C" void kernel_launch(void* const* d_in, const int* in_sizes, int n_in,
                              void* d_out, int out_size)
{
    (void)in_sizes; (void)n_in; (void)out_size;
    const float* x = (const float*)d_in[0];
    float* out = (float*)d_out;
    iqi3d_kernel<<<MAIN_BLOCKS + COPY_BLOCKS, 128>>>(x, out);
}